// round 1
// baseline (speedup 1.0000x reference)
#include <cuda_runtime.h>
#include <math.h>

// Problem shape (fixed by the reference):
//   memory:    [B=256, M=8192, W=32] f32
//   keys:      [B, H=4, W=32] f32
//   strengths: [B, H] f32
//   out:       [B, H, M] f32  = softmax_M( cos(keys, memory) * softplus(strengths) )

#define NB   256
#define MM   8192
#define WW   32
#define HH   4
#define EPSF 1e-5f
#define NT   1024
#define RPT  (MM / NT)   // 8 rows per thread

__global__ __launch_bounds__(NT, 1)
void weightfn_kernel(const float* __restrict__ mem,
                     const float* __restrict__ keys,
                     const float* __restrict__ strengths,
                     float* __restrict__ out)
{
    __shared__ float4 sk4[HH][WW / 4];   // keys for this batch
    __shared__ float  skn[HH];           // key norms
    __shared__ float  sbeta[HH];         // softplus(strength)
    __shared__ float  red[HH][32];       // cross-warp reduction scratch
    __shared__ float  gval[HH];          // block-wide result (max, then sum)

    const int b    = blockIdx.x;
    const int tid  = threadIdx.x;
    const int lane = tid & 31;
    const int wid  = tid >> 5;

    // ---- load keys for this batch into shared ----
    if (tid < HH * WW) {
        ((float*)sk4)[tid] = keys[b * HH * WW + tid];
    }
    __syncthreads();
    if (tid < HH) {
        float s = strengths[b * HH + tid];
        sbeta[tid] = (s > 20.0f) ? s : log1pf(__expf(s));  // softplus
        const float* k = (const float*)sk4[tid];
        float sq = 0.0f;
        #pragma unroll
        for (int w = 0; w < WW; w++) sq = fmaf(k[w], k[w], sq);
        skn[tid] = sqrtf(sq + EPSF);
    }
    __syncthreads();

    const float4* mp = (const float4*)(mem + (size_t)b * MM * WW);
    float* ob = out + (size_t)b * HH * MM;

    // ---- pass 1: sharp logits -> own slice of out; track per-thread max ----
    float lmax[HH];
    #pragma unroll
    for (int h = 0; h < HH; h++) lmax[h] = -INFINITY;

    #pragma unroll
    for (int r = 0; r < RPT; r++) {
        const int row = tid + r * NT;
        const float4* rp = mp + row * (WW / 4);
        float dot[HH] = {0.f, 0.f, 0.f, 0.f};
        float sq = 0.f;
        #pragma unroll
        for (int c = 0; c < WW / 4; c++) {
            float4 mv = rp[c];
            sq = fmaf(mv.x, mv.x, fmaf(mv.y, mv.y,
                 fmaf(mv.z, mv.z, fmaf(mv.w, mv.w, sq))));
            #pragma unroll
            for (int h = 0; h < HH; h++) {
                float4 kv = sk4[h][c];
                dot[h] = fmaf(mv.x, kv.x, fmaf(mv.y, kv.y,
                         fmaf(mv.z, kv.z, fmaf(mv.w, kv.w, dot[h]))));
            }
        }
        const float mn = sqrtf(sq + EPSF);
        #pragma unroll
        for (int h = 0; h < HH; h++) {
            // dot / (kn*mn + eps) * beta
            float v = dot[h] * __fdividef(sbeta[h], fmaf(skn[h], mn, EPSF));
            ob[h * MM + row] = v;
            lmax[h] = fmaxf(lmax[h], v);
        }
    }

    // ---- block-wide max per h ----
    #pragma unroll
    for (int s = 16; s > 0; s >>= 1) {
        #pragma unroll
        for (int h = 0; h < HH; h++)
            lmax[h] = fmaxf(lmax[h], __shfl_xor_sync(0xffffffff, lmax[h], s));
    }
    if (lane == 0) {
        #pragma unroll
        for (int h = 0; h < HH; h++) red[h][wid] = lmax[h];
    }
    __syncthreads();
    if (wid == 0) {
        float v[HH];
        #pragma unroll
        for (int h = 0; h < HH; h++) v[h] = red[h][lane];
        #pragma unroll
        for (int s = 16; s > 0; s >>= 1) {
            #pragma unroll
            for (int h = 0; h < HH; h++)
                v[h] = fmaxf(v[h], __shfl_xor_sync(0xffffffff, v[h], s));
        }
        if (lane == 0) {
            #pragma unroll
            for (int h = 0; h < HH; h++) gval[h] = v[h];
        }
    }
    __syncthreads();
    float gmax[HH];
    #pragma unroll
    for (int h = 0; h < HH; h++) gmax[h] = gval[h];

    // ---- pass 2: exp-sum (re-read own slice; hits L2/L1) ----
    float lsum[HH] = {0.f, 0.f, 0.f, 0.f};
    #pragma unroll
    for (int r = 0; r < RPT; r++) {
        const int row = tid + r * NT;
        #pragma unroll
        for (int h = 0; h < HH; h++)
            lsum[h] += __expf(ob[h * MM + row] - gmax[h]);
    }
    #pragma unroll
    for (int s = 16; s > 0; s >>= 1) {
        #pragma unroll
        for (int h = 0; h < HH; h++)
            lsum[h] += __shfl_xor_sync(0xffffffff, lsum[h], s);
    }
    __syncthreads();   // red[] reuse: everyone is past the max phase
    if (lane == 0) {
        #pragma unroll
        for (int h = 0; h < HH; h++) red[h][wid] = lsum[h];
    }
    __syncthreads();
    if (wid == 0) {
        float v[HH];
        #pragma unroll
        for (int h = 0; h < HH; h++) v[h] = red[h][lane];
        #pragma unroll
        for (int s = 16; s > 0; s >>= 1) {
            #pragma unroll
            for (int h = 0; h < HH; h++)
                v[h] += __shfl_xor_sync(0xffffffff, v[h], s);
        }
        if (lane == 0) {
            #pragma unroll
            for (int h = 0; h < HH; h++) gval[h] = v[h];
        }
    }
    __syncthreads();
    float inv[HH];
    #pragma unroll
    for (int h = 0; h < HH; h++) inv[h] = __fdividef(1.0f, gval[h]);

    // ---- pass 3: normalize in place (same addresses this thread wrote) ----
    #pragma unroll
    for (int r = 0; r < RPT; r++) {
        const int row = tid + r * NT;
        #pragma unroll
        for (int h = 0; h < HH; h++) {
            const int idx = h * MM + row;
            float v = ob[idx];
            ob[idx] = __expf(v - gmax[h]) * inv[h];
        }
    }
}

extern "C" void kernel_launch(void* const* d_in, const int* in_sizes, int n_in,
                              void* d_out, int out_size)
{
    const float* mem       = (const float*)d_in[0];
    const float* keys      = (const float*)d_in[1];
    const float* strengths = (const float*)d_in[2];
    float* out             = (float*)d_out;

    weightfn_kernel<<<NB, NT>>>(mem, keys, strengths, out);
}

// round 2
// speedup vs baseline: 2.3166x; 2.3166x over previous
#include <cuda_runtime.h>
#include <math.h>

// memory: [B=256, M=8192, W=32] f32 ; keys: [B,H=4,W=32] ; strengths: [B,H]
// out[b,h,m] = softmax_M( dot/(kn*mn+eps) * softplus(strength) )
// Trick: v <= beta always (|cos|<1), so shift softmax by beta -> sum is
// associative -> split M across blocks, partial sums, rescale in kernel 2.

#define NB      256
#define MM      8192
#define WW      32
#define HH      4
#define EPSF    1e-5f
#define SPLITS  8
#define NT1     256
#define ROWS_PER_BLOCK (MM / SPLITS)                 // 1024
#define NWARPS  (NT1 / 32)                           // 8
#define ROWS_PER_WARP  (ROWS_PER_BLOCK / NWARPS)     // 128
#define ITERS   (ROWS_PER_WARP / 8)                  // 16 (8 rows per warp-iter)

__device__ float g_partial[NB * HH * SPLITS];

__global__ __launch_bounds__(NT1)
void weightfn_k1(const float* __restrict__ mem,
                 const float* __restrict__ keys,
                 const float* __restrict__ strengths,
                 float* __restrict__ out)
{
    __shared__ float4 sk4[HH][WW / 4];
    __shared__ float  skn[HH];
    __shared__ float  sbeta[HH];
    __shared__ float  sred[NWARPS][4];

    const int bidx = blockIdx.x;
    const int b    = bidx >> 3;        // / SPLITS
    const int seg  = bidx & (SPLITS - 1);
    const int tid  = threadIdx.x;
    const int lane = tid & 31;
    const int wid  = tid >> 5;
    const int sub  = lane & 3;         // which quarter of the row / which h
    const int g    = lane >> 2;        // row within the 8-row group

    if (tid < HH * WW)
        ((float*)sk4)[tid] = keys[b * HH * WW + tid];
    __syncthreads();
    if (tid < HH) {
        float s = strengths[b * HH + tid];
        sbeta[tid] = (s > 20.0f) ? s : log1pf(__expf(s));
        const float* k = (const float*)sk4[tid];
        float sq = 0.0f;
        #pragma unroll
        for (int w = 0; w < WW; w++) sq = fmaf(k[w], k[w], sq);
        skn[tid] = sqrtf(sq + EPSF);
    }
    __syncthreads();

    // per-lane constants for its h = sub
    const float beta_h = sbeta[sub];
    const float kn_h   = skn[sub];
    // this lane's 8 key floats per h (hoisted; loop-invariant)
    float4 kA[HH], kB[HH];
    #pragma unroll
    for (int h = 0; h < HH; h++) {
        kA[h] = sk4[h][sub * 2];
        kB[h] = sk4[h][sub * 2 + 1];
    }

    const float4* mp4 = (const float4*)mem + (size_t)b * MM * (WW / 4);
    float* ob = out + (size_t)b * HH * MM;

    const int warpRow0 = seg * ROWS_PER_BLOCK + wid * ROWS_PER_WARP;
    float lsum = 0.0f;

    #pragma unroll 4
    for (int i = 0; i < ITERS; i++) {
        const int row = warpRow0 + i * 8 + g;
        const float4 m0 = mp4[row * 8 + sub * 2];
        const float4 m1 = mp4[row * 8 + sub * 2 + 1];

        float sq = fmaf(m0.x, m0.x, fmaf(m0.y, m0.y,
                   fmaf(m0.z, m0.z, fmaf(m0.w, m0.w, 0.0f))));
        sq = fmaf(m1.x, m1.x, fmaf(m1.y, m1.y,
             fmaf(m1.z, m1.z, fmaf(m1.w, m1.w, sq))));

        float dot[HH];
        #pragma unroll
        for (int h = 0; h < HH; h++) {
            float d = fmaf(m0.x, kA[h].x, fmaf(m0.y, kA[h].y,
                      fmaf(m0.z, kA[h].z, fmaf(m0.w, kA[h].w, 0.0f))));
            d = fmaf(m1.x, kB[h].x, fmaf(m1.y, kB[h].y,
                fmaf(m1.z, kB[h].z, fmaf(m1.w, kB[h].w, d))));
            dot[h] = d;
        }

        // reduce across the 4 lanes sharing this row
        #pragma unroll
        for (int mask = 1; mask <= 2; mask <<= 1) {
            sq += __shfl_xor_sync(0xffffffffu, sq, mask);
            #pragma unroll
            for (int h = 0; h < HH; h++)
                dot[h] += __shfl_xor_sync(0xffffffffu, dot[h], mask);
        }

        // lane 'sub' handles h = sub for this row (constant-index select)
        float d  = (sub == 0) ? dot[0] : (sub == 1) ? dot[1]
                 : (sub == 2) ? dot[2] : dot[3];
        const float mn = sqrtf(sq + EPSF);
        const float v  = d * __fdividef(beta_h, fmaf(kn_h, mn, EPSF));
        const float e  = __expf(v - beta_h);   // v <= beta -> e <= 1
        ob[sub * MM + row] = e;
        lsum += e;
    }

    // warp reduce: sum over the 8 lanes with the same sub (=h)
    #pragma unroll
    for (int mask = 4; mask <= 16; mask <<= 1)
        lsum += __shfl_xor_sync(0xffffffffu, lsum, mask);
    if (lane < 4) sred[wid][lane] = lsum;
    __syncthreads();

    if (tid < 32) {
        float v = sred[tid >> 2][tid & 3];   // 8 warps x 4 h
        #pragma unroll
        for (int mask = 4; mask <= 16; mask <<= 1)
            v += __shfl_xor_sync(0xffffffffu, v, mask);
        if (tid < 4)
            g_partial[(b * HH + tid) * SPLITS + seg] = v;
    }
}

__global__ __launch_bounds__(1024)
void weightfn_k2(float* __restrict__ out)
{
    __shared__ float sinv[HH];
    const int b   = blockIdx.x;
    const int tid = threadIdx.x;

    if (tid < HH) {
        float s = 0.0f;
        #pragma unroll
        for (int j = 0; j < SPLITS; j++)
            s += g_partial[(b * HH + tid) * SPLITS + j];
        sinv[tid] = __fdividef(1.0f, s);
    }
    __syncthreads();

    float4* o4 = (float4*)out + (size_t)b * HH * MM / 4;   // 8192 float4
    #pragma unroll
    for (int k = 0; k < 8; k++) {
        const int idx = tid + k * 1024;
        const float inv = sinv[idx >> 11];     // 2048 float4 per h
        float4 v = o4[idx];
        v.x *= inv; v.y *= inv; v.z *= inv; v.w *= inv;
        o4[idx] = v;
    }
}

extern "C" void kernel_launch(void* const* d_in, const int* in_sizes, int n_in,
                              void* d_out, int out_size)
{
    const float* mem       = (const float*)d_in[0];
    const float* keys      = (const float*)d_in[1];
    const float* strengths = (const float*)d_in[2];
    float* out             = (float*)d_out;

    weightfn_k1<<<NB * SPLITS, NT1>>>(mem, keys, strengths, out);
    weightfn_k2<<<NB, 1024>>>(out);
}

// round 3
// speedup vs baseline: 2.6443x; 1.1414x over previous
#include <cuda_runtime.h>
#include <math.h>

// memory: [B=256, M=8192, W=32] f32 ; keys: [B,H=4,W=32] ; strengths: [B,H]
// out[b,h,m] = softmax_M( dot/(kn*mn+eps) * softplus(strength) )
// v <= beta always (|cos|<1): shift softmax by beta -> associative sum ->
// split M across blocks, partial sums to __device__ array, rescale in k2.

#define NB      256
#define MM      8192
#define WW      32
#define HH      4
#define EPSF    1e-5f
#define SPLITS  16
#define NT1     256
#define ROWS_PER_BLOCK (MM / SPLITS)                 // 512
#define NWARPS  (NT1 / 32)                           // 8
#define ROWS_PER_WARP  (ROWS_PER_BLOCK / NWARPS)     // 64
#define ITERS   (ROWS_PER_WARP / 8)                  // 8 (8 rows per warp-iter)

__device__ float g_partial[NB * HH * SPLITS];

__global__ __launch_bounds__(NT1)
void weightfn_k1(const float* __restrict__ mem,
                 const float* __restrict__ keys,
                 const float* __restrict__ strengths,
                 float* __restrict__ out)
{
    __shared__ float4 sk4[HH][WW / 4];
    __shared__ float  skn[HH];
    __shared__ float  sbeta[HH];
    __shared__ float  sred[NWARPS][4];

    const int bidx = blockIdx.x;
    const int b    = bidx >> 4;              // / SPLITS
    const int seg  = bidx & (SPLITS - 1);
    const int tid  = threadIdx.x;
    const int lane = tid & 31;
    const int wid  = tid >> 5;
    const int sub  = lane & 3;               // quarter of row / h index
    const int g    = lane >> 2;              // row within the 8-row group

    if (tid < HH * WW)
        ((float*)sk4)[tid] = keys[b * HH * WW + tid];
    __syncthreads();
    if (tid < HH) {
        float s = strengths[b * HH + tid];
        sbeta[tid] = (s > 20.0f) ? s : log1pf(__expf(s));
        const float* k = (const float*)sk4[tid];
        float sq = 0.0f;
        #pragma unroll
        for (int w = 0; w < WW; w++) sq = fmaf(k[w], k[w], sq);
        skn[tid] = sqrtf(sq + EPSF);
    }
    __syncthreads();

    const float beta_h = sbeta[sub];
    const float kn_h   = skn[sub];
    float4 kA[HH], kB[HH];
    #pragma unroll
    for (int h = 0; h < HH; h++) {
        kA[h] = sk4[h][sub * 2];
        kB[h] = sk4[h][sub * 2 + 1];
    }

    const float4* mp4 = (const float4*)mem + (size_t)b * MM * (WW / 4);
    float* ob = out + (size_t)b * HH * MM;

    const int warpRow0 = seg * ROWS_PER_BLOCK + wid * ROWS_PER_WARP;
    float lsum = 0.0f;

    #pragma unroll
    for (int i = 0; i < ITERS; i++) {
        const int row = warpRow0 + i * 8 + g;
        const float4 m0 = __ldcs(&mp4[row * 8 + sub * 2]);
        const float4 m1 = __ldcs(&mp4[row * 8 + sub * 2 + 1]);

        float sq = fmaf(m0.x, m0.x, fmaf(m0.y, m0.y,
                   fmaf(m0.z, m0.z, fmaf(m0.w, m0.w, 0.0f))));
        sq = fmaf(m1.x, m1.x, fmaf(m1.y, m1.y,
             fmaf(m1.z, m1.z, fmaf(m1.w, m1.w, sq))));

        float dot[HH];
        #pragma unroll
        for (int h = 0; h < HH; h++) {
            float d = fmaf(m0.x, kA[h].x, fmaf(m0.y, kA[h].y,
                      fmaf(m0.z, kA[h].z, fmaf(m0.w, kA[h].w, 0.0f))));
            d = fmaf(m1.x, kB[h].x, fmaf(m1.y, kB[h].y,
                fmaf(m1.z, kB[h].z, fmaf(m1.w, kB[h].w, d))));
            dot[h] = d;
        }

        #pragma unroll
        for (int mask = 1; mask <= 2; mask <<= 1) {
            sq += __shfl_xor_sync(0xffffffffu, sq, mask);
            #pragma unroll
            for (int h = 0; h < HH; h++)
                dot[h] += __shfl_xor_sync(0xffffffffu, dot[h], mask);
        }

        float d  = (sub == 0) ? dot[0] : (sub == 1) ? dot[1]
                 : (sub == 2) ? dot[2] : dot[3];
        const float mn = sqrtf(sq + EPSF);
        const float v  = d * __fdividef(beta_h, fmaf(kn_h, mn, EPSF));
        const float e  = __expf(v - beta_h);   // <= 1
        ob[sub * MM + row] = e;
        lsum += e;
    }

    // sum over the 8 lanes sharing this sub (=h)
    #pragma unroll
    for (int mask = 4; mask <= 16; mask <<= 1)
        lsum += __shfl_xor_sync(0xffffffffu, lsum, mask);
    if (lane < 4) sred[wid][lane] = lsum;
    __syncthreads();

    if (tid < 32) {
        float v = sred[tid >> 2][tid & 3];   // 8 warps x 4 h
        #pragma unroll
        for (int mask = 4; mask <= 16; mask <<= 1)
            v += __shfl_xor_sync(0xffffffffu, v, mask);
        if (tid < 4)
            g_partial[(b * HH + tid) * SPLITS + seg] = v;
    }
}

// 2048 blocks x 256 threads; one (b,h) per block, 4096 floats each.
__global__ __launch_bounds__(256)
void weightfn_k2(float* __restrict__ out)
{
    __shared__ float sinv;
    const int bidx = blockIdx.x;
    const int b    = bidx >> 3;
    const int seg  = bidx & 7;        // 2 segs per h
    const int h    = seg >> 1;
    const int tid  = threadIdx.x;

    if (tid < 16) {
        float v = g_partial[(b * HH + h) * SPLITS + tid];
        #pragma unroll
        for (int mask = 1; mask <= 8; mask <<= 1)
            v += __shfl_xor_sync(0xffffu, v, mask);
        if (tid == 0) sinv = __fdividef(1.0f, v);
    }
    __syncthreads();

    const float inv = sinv;
    float4* o4 = (float4*)out + (size_t)b * HH * MM / 4 + seg * 1024;
    #pragma unroll
    for (int k = 0; k < 4; k++) {
        const int idx = tid + k * 256;
        float4 v = o4[idx];
        v.x *= inv; v.y *= inv; v.z *= inv; v.w *= inv;
        __stcs(&o4[idx], v);
    }
}

extern "C" void kernel_launch(void* const* d_in, const int* in_sizes, int n_in,
                              void* d_out, int out_size)
{
    const float* mem       = (const float*)d_in[0];
    const float* keys      = (const float*)d_in[1];
    const float* strengths = (const float*)d_in[2];
    float* out             = (float*)d_out;

    weightfn_k1<<<NB * SPLITS, NT1>>>(mem, keys, strengths, out);
    weightfn_k2<<<NB * 8, 256>>>(out);
}

// round 5
// speedup vs baseline: 2.7717x; 1.0482x over previous
#include <cuda_runtime.h>
#include <math.h>

// memory: [B=256, M=8192, W=32] f32 ; keys: [B,H=4,W=32] ; strengths: [B,H]
// out[b,h,m] = softmax_M( dot/(kn*mn+eps) * softplus(strength) )
// |cos|<1 -> v <= beta: shift softmax by beta, no max pass needed.
// One block per batch (512 thr, occ 2/SM -> 256 blocks in ONE wave):
// pass1 compute e + block sum, pass2 normalize from L2-resident slice.

#define NB    256
#define MM    8192
#define WW    32
#define HH    4
#define EPSF  1e-5f
#define NT    512
#define NW    (NT / 32)              // 16 warps
#define RPW   (MM / NW)              // 512 rows per warp
#define ITERS (RPW / 8)              // 64 iterations, 8 rows per warp-iter

__global__ __launch_bounds__(NT, 2)
void weightfn_fused(const float* __restrict__ mem,
                    const float* __restrict__ keys,
                    const float* __restrict__ strengths,
                    float* __restrict__ out)
{
    __shared__ float4 sk4[HH][WW / 4];
    __shared__ float  skn[HH];
    __shared__ float  sbeta[HH];
    __shared__ float  sred[NW][4];
    __shared__ float  sinv[HH];

    const int b    = blockIdx.x;
    const int tid  = threadIdx.x;
    const int lane = tid & 31;
    const int wid  = tid >> 5;
    const int sub  = lane & 3;       // quarter of row, also h index
    const int g    = lane >> 2;      // row within 8-row group

    if (tid < HH * WW)
        ((float*)sk4)[tid] = keys[b * HH * WW + tid];
    __syncthreads();
    if (tid < HH) {
        float s = strengths[b * HH + tid];
        sbeta[tid] = (s > 20.0f) ? s : log1pf(__expf(s));
        const float* k = (const float*)sk4[tid];
        float sq = 0.0f;
        #pragma unroll
        for (int w = 0; w < WW; w++) sq = fmaf(k[w], k[w], sq);
        skn[tid] = sqrtf(sq + EPSF);
    }
    __syncthreads();

    const float beta_h = sbeta[sub];
    const float kn_h   = skn[sub];
    float4 kA[HH], kB[HH];
    #pragma unroll
    for (int h = 0; h < HH; h++) {
        kA[h] = sk4[h][sub * 2];
        kB[h] = sk4[h][sub * 2 + 1];
    }

    const float4* mp4 = (const float4*)mem + (size_t)b * MM * (WW / 4);
    float* ob = out + (size_t)b * HH * MM;

    const int warpRow0 = wid * RPW;
    float lsum = 0.0f;

    // ---- pass 1: e = exp(sharp - beta), streamed reads ----
    #pragma unroll 4
    for (int i = 0; i < ITERS; i++) {
        const int row = warpRow0 + i * 8 + g;
        const float4 m0 = __ldcs(&mp4[row * 8 + sub * 2]);
        const float4 m1 = __ldcs(&mp4[row * 8 + sub * 2 + 1]);

        float sq = fmaf(m0.x, m0.x, fmaf(m0.y, m0.y,
                   fmaf(m0.z, m0.z, fmaf(m0.w, m0.w, 0.0f))));
        sq = fmaf(m1.x, m1.x, fmaf(m1.y, m1.y,
             fmaf(m1.z, m1.z, fmaf(m1.w, m1.w, sq))));

        float dot[HH];
        #pragma unroll
        for (int h = 0; h < HH; h++) {
            float d = fmaf(m0.x, kA[h].x, fmaf(m0.y, kA[h].y,
                      fmaf(m0.z, kA[h].z, fmaf(m0.w, kA[h].w, 0.0f))));
            d = fmaf(m1.x, kB[h].x, fmaf(m1.y, kB[h].y,
                fmaf(m1.z, kB[h].z, fmaf(m1.w, kB[h].w, d))));
            dot[h] = d;
        }

        #pragma unroll
        for (int mask = 1; mask <= 2; mask <<= 1) {
            sq += __shfl_xor_sync(0xffffffffu, sq, mask);
            #pragma unroll
            for (int h = 0; h < HH; h++)
                dot[h] += __shfl_xor_sync(0xffffffffu, dot[h], mask);
        }

        float d  = (sub == 0) ? dot[0] : (sub == 1) ? dot[1]
                 : (sub == 2) ? dot[2] : dot[3];
        const float mn = sqrtf(sq + EPSF);
        const float v  = d * __fdividef(beta_h, fmaf(kn_h, mn, EPSF));
        const float e  = __expf(v - beta_h);     // <= 1
        ob[sub * MM + row] = e;
        lsum += e;
    }

    // ---- block-wide sum per h ----
    #pragma unroll
    for (int mask = 4; mask <= 16; mask <<= 1)
        lsum += __shfl_xor_sync(0xffffffffu, lsum, mask);
    if (lane < 4) sred[wid][lane] = lsum;
    __syncthreads();

    if (tid < 32) {
        // 16 warps x 4 h = 64 values; fold 2 warps per lane then reduce
        float v = sred[lane >> 2][lane & 3] + sred[8 + (lane >> 2)][lane & 3];
        #pragma unroll
        for (int mask = 4; mask <= 16; mask <<= 1)
            v += __shfl_xor_sync(0xffffffffu, v, mask);
        if (lane < 4) sinv[lane] = __fdividef(1.0f, v);
    }
    __syncthreads();

    // ---- pass 2: normalize (L2-resident slice), coalesced float4 ----
    float4* o4 = (float4*)ob;                     // 8192 float4 (2048 per h)
    #pragma unroll
    for (int k = 0; k < 16; k++) {
        const int idx = tid + k * NT;
        const float inv = sinv[idx >> 11];
        float4 v = o4[idx];
        v.x *= inv; v.y *= inv; v.z *= inv; v.w *= inv;
        __stcs(&o4[idx], v);
    }
}

extern "C" void kernel_launch(void* const* d_in, const int* in_sizes, int n_in,
                              void* d_out, int out_size)
{
    const float* mem       = (const float*)d_in[0];
    const float* keys      = (const float*)d_in[1];
    const float* strengths = (const float*)d_in[2];
    float* out             = (float*)d_out;

    weightfn_fused<<<NB, NT>>>(mem, keys, strengths, out);
}

// round 7
// speedup vs baseline: 3.0506x; 1.1006x over previous
#include <cuda_runtime.h>
#include <math.h>
#include <cstdint>

// memory: [B=256, M=8192, W=32] f32 ; keys: [B,H=4,W=32] ; strengths: [B,H]
// out[b,h,m] = softmax_M( dot/(kn*mn+eps) * softplus(strength) )
// |cos|<1 -> v <= beta: shift softmax by beta -> associative sum ->
// split M across blocks; partial sums in __device__ array; k2 rescales.

#define NB      256
#define MM      8192
#define WW      32
#define HH      4
#define EPSF    1e-5f
#define SPLITS  16
#define NT1     256
#define ROWS_PER_BLOCK (MM / SPLITS)                 // 512
#define NWARPS  (NT1 / 32)                           // 8
#define ROWS_PER_WARP  (ROWS_PER_BLOCK / NWARPS)     // 64
#define ITERS   (ROWS_PER_WARP / 8)                  // 8 (8 rows / warp-iter)

__device__ float g_partial[NB * HH * SPLITS];

// un-hoistable shared load: keeps key data out of the register file
__device__ __forceinline__ float4 lds128(uint32_t addr) {
    float4 v;
    asm volatile("ld.shared.v4.f32 {%0,%1,%2,%3}, [%4];"
        : "=f"(v.x), "=f"(v.y), "=f"(v.z), "=f"(v.w) : "r"(addr));
    return v;
}

__global__ __launch_bounds__(NT1, 6)
void weightfn_k1(const float* __restrict__ mem,
                 const float* __restrict__ keys,
                 const float* __restrict__ strengths,
                 float* __restrict__ out)
{
    __shared__ float4 sk4[HH][WW / 4];   // keys, [h][chunk]
    __shared__ float  skn[HH];
    __shared__ float  sbeta[HH];
    __shared__ float  sred[NWARPS][4];

    const int bidx = blockIdx.x;
    const int b    = bidx >> 4;              // / SPLITS
    const int seg  = bidx & (SPLITS - 1);
    const int tid  = threadIdx.x;
    const int lane = tid & 31;
    const int wid  = tid >> 5;
    const int sub  = lane & 3;               // quarter of row / h index
    const int g    = lane >> 2;              // row within 8-row group

    if (tid < HH * WW)
        ((float*)sk4)[tid] = keys[b * HH * WW + tid];
    __syncthreads();
    if (tid < HH) {
        float s = strengths[b * HH + tid];
        sbeta[tid] = (s > 20.0f) ? s : log1pf(__expf(s));
        const float* k = (const float*)sk4[tid];
        float sq = 0.0f;
        #pragma unroll
        for (int w = 0; w < WW; w++) sq = fmaf(k[w], k[w], sq);
        skn[tid] = sqrtf(sq + EPSF);
    }
    __syncthreads();

    const float beta_h = sbeta[sub];
    const float kn_h   = skn[sub];

    // shared base address of this lane's key quarter: sk4[0][sub*2]
    const uint32_t skbase =
        (uint32_t)__cvta_generic_to_shared(&sk4[0][0]) + (uint32_t)(sub * 32);

    const float4* mp4 = (const float4*)mem + (size_t)b * MM * (WW / 4);
    float* ob = out + (size_t)b * HH * MM;

    const int warpRow0 = seg * ROWS_PER_BLOCK + wid * ROWS_PER_WARP;
    float lsum = 0.0f;

    #pragma unroll
    for (int i = 0; i < ITERS; i += 2) {
        const int rowA = warpRow0 + i * 8 + g;
        const int rowB = rowA + 8;
        // 4 LDG.128 front-batched (MLP 4)
        const float4 a0 = __ldcs(&mp4[rowA * 8 + sub * 2]);
        const float4 a1 = __ldcs(&mp4[rowA * 8 + sub * 2 + 1]);
        const float4 b0 = __ldcs(&mp4[rowB * 8 + sub * 2]);
        const float4 b1 = __ldcs(&mp4[rowB * 8 + sub * 2 + 1]);

        float sqA = fmaf(a0.x, a0.x, fmaf(a0.y, a0.y,
                    fmaf(a0.z, a0.z, fmaf(a0.w, a0.w, 0.0f))));
        sqA = fmaf(a1.x, a1.x, fmaf(a1.y, a1.y,
              fmaf(a1.z, a1.z, fmaf(a1.w, a1.w, sqA))));
        float sqB = fmaf(b0.x, b0.x, fmaf(b0.y, b0.y,
                    fmaf(b0.z, b0.z, fmaf(b0.w, b0.w, 0.0f))));
        sqB = fmaf(b1.x, b1.x, fmaf(b1.y, b1.y,
              fmaf(b1.z, b1.z, fmaf(b1.w, b1.w, sqB))));

        float dotA[HH], dotB[HH];
        #pragma unroll
        for (int h = 0; h < HH; h++) {
            // keys read from smem each time (8 LDS.128 per 2 row-groups)
            const float4 k0 = lds128(skbase + (uint32_t)(h * 128));
            const float4 k1 = lds128(skbase + (uint32_t)(h * 128 + 16));
            float dA = fmaf(a0.x, k0.x, fmaf(a0.y, k0.y,
                       fmaf(a0.z, k0.z, fmaf(a0.w, k0.w, 0.0f))));
            dA = fmaf(a1.x, k1.x, fmaf(a1.y, k1.y,
                 fmaf(a1.z, k1.z, fmaf(a1.w, k1.w, dA))));
            float dB = fmaf(b0.x, k0.x, fmaf(b0.y, k0.y,
                       fmaf(b0.z, k0.z, fmaf(b0.w, k0.w, 0.0f))));
            dB = fmaf(b1.x, k1.x, fmaf(b1.y, k1.y,
                 fmaf(b1.z, k1.z, fmaf(b1.w, k1.w, dB))));
            dotA[h] = dA;
            dotB[h] = dB;
        }

        #pragma unroll
        for (int mask = 1; mask <= 2; mask <<= 1) {
            sqA += __shfl_xor_sync(0xffffffffu, sqA, mask);
            sqB += __shfl_xor_sync(0xffffffffu, sqB, mask);
            #pragma unroll
            for (int h = 0; h < HH; h++) {
                dotA[h] += __shfl_xor_sync(0xffffffffu, dotA[h], mask);
                dotB[h] += __shfl_xor_sync(0xffffffffu, dotB[h], mask);
            }
        }

        float dA = (sub == 0) ? dotA[0] : (sub == 1) ? dotA[1]
                 : (sub == 2) ? dotA[2] : dotA[3];
        float dB = (sub == 0) ? dotB[0] : (sub == 1) ? dotB[1]
                 : (sub == 2) ? dotB[2] : dotB[3];

        const float mnA = sqrtf(sqA + EPSF);
        const float mnB = sqrtf(sqB + EPSF);
        const float vA = dA * __fdividef(beta_h, fmaf(kn_h, mnA, EPSF));
        const float vB = dB * __fdividef(beta_h, fmaf(kn_h, mnB, EPSF));
        const float eA = __expf(vA - beta_h);
        const float eB = __expf(vB - beta_h);
        ob[sub * MM + rowA] = eA;
        ob[sub * MM + rowB] = eB;
        lsum += eA + eB;
    }

    // sum over 8 lanes sharing this sub (=h)
    #pragma unroll
    for (int mask = 4; mask <= 16; mask <<= 1)
        lsum += __shfl_xor_sync(0xffffffffu, lsum, mask);
    if (lane < 4) sred[wid][lane] = lsum;
    __syncthreads();

    if (tid < 32) {
        float v = sred[tid >> 2][tid & 3];   // 8 warps x 4 h
        #pragma unroll
        for (int mask = 4; mask <= 16; mask <<= 1)
            v += __shfl_xor_sync(0xffffffffu, v, mask);
        if (tid < 4)
            g_partial[(b * HH + tid) * SPLITS + seg] = v;
    }
}

// 2048 blocks x 256 thr; one (b,h,half) per block -> scalar inv, MLP 4.
__global__ __launch_bounds__(256, 8)
void weightfn_k2(float* __restrict__ out)
{
    __shared__ float sinv;
    const int bidx = blockIdx.x;
    const int b    = bidx >> 3;
    const int rest = bidx & 7;
    const int h    = rest >> 1;
    const int half = rest & 1;
    const int tid  = threadIdx.x;

    if (tid < 16) {
        float v = g_partial[(b * HH + h) * SPLITS + tid];
        #pragma unroll
        for (int mask = 1; mask <= 8; mask <<= 1)
            v += __shfl_xor_sync(0xffffu, v, mask);
        if (tid == 0) sinv = __fdividef(1.0f, v);
    }

    float4* o4 = (float4*)out + ((size_t)(b * HH + h) * MM) / 4 + half * 1024;
    // front-batch all 4 loads (MLP 4), mostly L2 hits
    float4 v0 = o4[tid];
    float4 v1 = o4[tid + 256];
    float4 v2 = o4[tid + 512];
    float4 v3 = o4[tid + 768];
    __syncthreads();
    const float inv = sinv;
    v0.x *= inv; v0.y *= inv; v0.z *= inv; v0.w *= inv;
    v1.x *= inv; v1.y *= inv; v1.z *= inv; v1.w *= inv;
    v2.x *= inv; v2.y *= inv; v2.z *= inv; v2.w *= inv;
    v3.x *= inv; v3.y *= inv; v3.z *= inv; v3.w *= inv;
    __stcs(&o4[tid],       v0);
    __stcs(&o4[tid + 256], v1);
    __stcs(&o4[tid + 512], v2);
    __stcs(&o4[tid + 768], v3);
}

extern "C" void kernel_launch(void* const* d_in, const int* in_sizes, int n_in,
                              void* d_out, int out_size)
{
    const float* mem       = (const float*)d_in[0];
    const float* keys      = (const float*)d_in[1];
    const float* strengths = (const float*)d_in[2];
    float* out             = (float*)d_out;

    weightfn_k1<<<NB * SPLITS, NT1>>>(mem, keys, strengths, out);
    weightfn_k2<<<NB * HH * 2, 256>>>(out);
}